// round 17
// baseline (speedup 1.0000x reference)
#include <cuda_runtime.h>

// Problem dims (fixed by the reference setup_inputs)
#define B_    256
#define F_    300
#define JC_   1600
#define NC_   60
#define J4_   (JC_ / 4)    // 400 float4 per frame
#define CHUNK 50           // frames per pooling tile
#define NCH   (F_ / CHUNK) // 6 chunks
#define NTILE (B_ * NCH)   // 1536 pooling tiles
#define NQ    (NC_ / 4)    // 15 n-quads
#define BTILE 8            // batch rows per fc task (1 row/warp)
#define BT_N  (B_ / BTILE) // 32 batch tiles
#define NFCT  (NQ * BT_N)  // 480 fc tasks
#define THREADS 400

// Pooled (un-normalized) feature sums [B, JC] — 1.6 MB
__device__ float    g_pooled[(size_t)B_ * JC_];
// Per-batch chunk-arrival counters (memset to 0 each launch)
__device__ unsigned g_done[B_];

__device__ __forceinline__ unsigned ld_acquire_gpu(const unsigned* p) {
    unsigned v;
    asm volatile("ld.global.acquire.gpu.u32 %0, [%1];" : "=r"(v) : "l"(p) : "memory");
    return v;
}

// ---------------------------------------------------------------------------
// Tail-fused kernel, occupancy 3 (the R16 regression was occ 2 cutting the
// pool's streaming MLP: 5.3 TB/s vs 6.9).  grid = NTILE + NFCT = 2016.
//  bid <  1536 : pool tile (proven body; b-major so batches finish early).
//  bid >= 1536 : FC task in the LAST wave. One batch row per warp (4 FMA
//                chains, 1 LDG + 1 LDS.128 per iter) fits the 53-reg budget
//                without serializing; W slice -> smem first; per-warp spin.
// ---------------------------------------------------------------------------
__global__ __launch_bounds__(THREADS, 3) void fused_kernel(
    const float* __restrict__ x,       // [B, F, JC]
    const int*   __restrict__ lengths, // [B]
    const float* __restrict__ W,       // [JC, NC] row-major
    const float* __restrict__ bias,    // [NC]
    float*       __restrict__ out)     // [B, NC]
{
    __shared__ float4 sW[JC_];         // 25.6 KB (FC role only); 3x fits 228KB

    const int bid = blockIdx.x;
    const int t   = threadIdx.x;

    if (bid < NTILE) {
        // ================= Pool role =================
        const int b = bid / NCH;       // b-major
        const int c = bid - b * NCH;
        const int len = lengths[b];
        const int f0 = c * CHUNK;

        if (f0 < len) {
            const int f1 = min(f0 + CHUNK, len);
            const float4* __restrict__ xb =
                reinterpret_cast<const float4*>(x + (size_t)b * F_ * JC_);
            const int j4 = t;

            float ax = 0.f, ay = 0.f, az = 0.f, aw = 0.f;
            int f = f0;
            for (; f + 8 <= f1; f += 8) {
                float4 v0 = __ldcs(&xb[(size_t)(f + 0) * J4_ + j4]);
                float4 v1 = __ldcs(&xb[(size_t)(f + 1) * J4_ + j4]);
                float4 v2 = __ldcs(&xb[(size_t)(f + 2) * J4_ + j4]);
                float4 v3 = __ldcs(&xb[(size_t)(f + 3) * J4_ + j4]);
                float4 v4 = __ldcs(&xb[(size_t)(f + 4) * J4_ + j4]);
                float4 v5 = __ldcs(&xb[(size_t)(f + 5) * J4_ + j4]);
                float4 v6 = __ldcs(&xb[(size_t)(f + 6) * J4_ + j4]);
                float4 v7 = __ldcs(&xb[(size_t)(f + 7) * J4_ + j4]);
                ax += (v0.x + v1.x) + (v2.x + v3.x) + ((v4.x + v5.x) + (v6.x + v7.x));
                ay += (v0.y + v1.y) + (v2.y + v3.y) + ((v4.y + v5.y) + (v6.y + v7.y));
                az += (v0.z + v1.z) + (v2.z + v3.z) + ((v4.z + v5.z) + (v6.z + v7.z));
                aw += (v0.w + v1.w) + (v2.w + v3.w) + ((v4.w + v5.w) + (v6.w + v7.w));
            }
            for (; f < f1; f++) {
                float4 v = __ldcs(&xb[(size_t)f * J4_ + j4]);
                ax += v.x; ay += v.y; az += v.z; aw += v.w;
            }
            float* dst = g_pooled + (size_t)b * JC_ + j4 * 4;
            asm volatile("red.global.add.v4.f32 [%0], {%1, %2, %3, %4};"
                         :: "l"(dst), "f"(ax), "f"(ay), "f"(az), "f"(aw)
                         : "memory");
        }

        // arrival: publish reds, then count (every pool block arrives)
        __threadfence();
        __syncthreads();
        if (t == 0) atomicAdd(&g_done[b], 1u);
        return;
    }

    // ================= FC role (last wave) =================
    {
        const int task = bid - NTILE;          // 0..479
        const int q  = task % NQ;              // 0..14
        const int b0 = (task / NQ) * BTILE;    // batch tile base (8 rows)

        // W slice -> smem (overlaps with the pool tail on other SMs)
        const float4* __restrict__ W4 = reinterpret_cast<const float4*>(W);
#pragma unroll
        for (int j = t; j < JC_; j += THREADS)
            sW[j] = W4[(size_t)j * NQ + q];
        __syncthreads();

        if (t >= 256) return;
        const int w = t >> 5;                  // 0..7 -> one batch row each
        const int l = t & 31;
        const int b = b0 + w;

        // per-warp spin until this batch is fully pooled
        while (ld_acquire_gpu(&g_done[b]) < (unsigned)NCH) __nanosleep(64);
        __syncwarp();

        const int len = lengths[b];
        const float* __restrict__ src = (len <= 1)
            ? (x + (size_t)b * F_ * JC_) : (g_pooled + (size_t)b * JC_);
        const float inv = (len <= 1) ? 1.0f : 1.0f / (float)len;

        float4 a0 = make_float4(0.f, 0.f, 0.f, 0.f);
#pragma unroll 8
        for (int k = 0; k < JC_ / 32; k++) {   // 50 iterations
            const int j = k * 32 + l;
            const float p = src[j];            // coalesced 128B warp load
            const float4 wv = sW[j];           // conflict-free LDS.128
            a0.x += p * wv.x; a0.y += p * wv.y;
            a0.z += p * wv.z; a0.w += p * wv.w;
        }
#pragma unroll
        for (int off = 16; off > 0; off >>= 1) {
            a0.x += __shfl_xor_sync(0xFFFFFFFF, a0.x, off);
            a0.y += __shfl_xor_sync(0xFFFFFFFF, a0.y, off);
            a0.z += __shfl_xor_sync(0xFFFFFFFF, a0.z, off);
            a0.w += __shfl_xor_sync(0xFFFFFFFF, a0.w, off);
        }
        if (l == 0) {
            const int n = 4 * q;
            float* o = out + (size_t)b * NC_ + n;
            o[0] = a0.x * inv + bias[n + 0];
            o[1] = a0.y * inv + bias[n + 1];
            o[2] = a0.z * inv + bias[n + 2];
            o[3] = a0.w * inv + bias[n + 3];
        }
    }
}

extern "C" void kernel_launch(void* const* d_in, const int* in_sizes, int n_in,
                              void* d_out, int out_size)
{
    const float* x       = (const float*)d_in[0];
    const int*   lengths = (const int*)  d_in[1];
    const float* W       = (const float*)d_in[2];
    const float* bias    = (const float*)d_in[3];
    float*       out     = (float*)d_out;

    // zero accumulator + counters (graph-capturable memset nodes)
    void* pooled_ptr = nullptr;
    cudaGetSymbolAddress(&pooled_ptr, g_pooled);
    cudaMemsetAsync(pooled_ptr, 0, sizeof(float) * (size_t)B_ * JC_);
    void* done_ptr = nullptr;
    cudaGetSymbolAddress(&done_ptr, g_done);
    cudaMemsetAsync(done_ptr, 0, sizeof(unsigned) * B_);

    fused_kernel<<<NTILE + NFCT, THREADS>>>(x, lengths, W, bias, out);
}